// round 1
// baseline (speedup 1.0000x reference)
#include <cuda_runtime.h>

#define NB 128
#define NT 4096
#define NTHREADS 1024
#define TOK 4              // tokens per thread: 1024*4 = 4096 = NT

__device__ __forceinline__ float ex2f_(float x) {
    float y; asm("ex2.approx.f32 %0, %1;" : "=f"(y) : "f"(x)); return y;
}
__device__ __forceinline__ float rcpf_(float x) {
    float y; asm("rcp.approx.f32 %0, %1;" : "=f"(y) : "f"(x)); return y;
}
// tanh(x) = 1 - 2 / (exp(2x) + 1), exp via ex2
__device__ __forceinline__ float ftanh_(float x) {
    float e = ex2f_(2.885390081777927f * x);   // 2 * log2(e) * x
    return fmaf(-2.0f, rcpf_(e + 1.0f), 1.0f);
}

__global__ void __launch_bounds__(NTHREADS, 1)
additive_attn_fused(const float* __restrict__ query,   // [B,1,16]
                    const float* __restrict__ key,     // [B,T,16]
                    const float* __restrict__ value,   // [B,T,16]
                    const float* __restrict__ W1,      // [32,16]
                    const float* __restrict__ W2,      // [32,16]
                    const float* __restrict__ bias,    // scalar
                    const float* __restrict__ v_w,     // [1,32]
                    const float* __restrict__ v_b,     // [1]
                    float* __restrict__ out_ctx,       // [B,16]
                    float* __restrict__ out_attn)      // [B,T]
{
    const int b    = blockIdx.x;
    const int tid  = threadIdx.x;
    const int lane = tid & 31;
    const int wid  = tid >> 5;

    __shared__ float4 sW2[128];       // 32 rows x 16 floats, as float4
    __shared__ float  sv[32];         // v_w
    __shared__ float  sc[32];         // per-batch q-projection + bias
    __shared__ float  sred[32 * 17];  // cross-warp reduction scratch
    __shared__ float  sbc[18];        // [0]=block max, [1]=sum, [2..17]=ctx

    // Stage weights + compute q projection (tiny) in shared
    if (tid < 128) sW2[tid] = reinterpret_cast<const float4*>(W2)[tid];
    if (tid >= 128 && tid < 160) sv[tid - 128] = v_w[tid - 128];
    if (tid >= 160 && tid < 192) {
        const int w = tid - 160;
        float acc = *bias;
        #pragma unroll
        for (int d = 0; d < 16; d++)
            acc = fmaf(query[b * 16 + d], W1[w * 16 + d], acc);
        sc[w] = acc;
    }
    __syncthreads();

    const float vb = *v_b;

    // ---------- Phase A: scores for this thread's 4 tokens ----------
    float s[TOK];
    #pragma unroll
    for (int j = 0; j < TOK; j++) {
        const int t = tid + j * NTHREADS;
        const float4* kp =
            reinterpret_cast<const float4*>(key + ((size_t)b * NT + t) * 16);
        const float4 k0 = kp[0], k1 = kp[1], k2 = kp[2], k3 = kp[3];

        float acc_s = vb;
        #pragma unroll 4
        for (int w = 0; w < 32; w++) {
            const float4 a0 = sW2[w * 4 + 0];
            const float4 a1 = sW2[w * 4 + 1];
            const float4 a2 = sW2[w * 4 + 2];
            const float4 a3 = sW2[w * 4 + 3];
            float a = sc[w];
            a = fmaf(a0.x, k0.x, a); a = fmaf(a0.y, k0.y, a);
            a = fmaf(a0.z, k0.z, a); a = fmaf(a0.w, k0.w, a);
            a = fmaf(a1.x, k1.x, a); a = fmaf(a1.y, k1.y, a);
            a = fmaf(a1.z, k1.z, a); a = fmaf(a1.w, k1.w, a);
            a = fmaf(a2.x, k2.x, a); a = fmaf(a2.y, k2.y, a);
            a = fmaf(a2.z, k2.z, a); a = fmaf(a2.w, k2.w, a);
            a = fmaf(a3.x, k3.x, a); a = fmaf(a3.y, k3.y, a);
            a = fmaf(a3.z, k3.z, a); a = fmaf(a3.w, k3.w, a);
            const float h = ftanh_(a);
            acc_s = fmaf(sv[w], h, acc_s);
        }
        s[j] = acc_s;
    }

    // ---------- Block max (exact, deterministic) ----------
    float m = s[0];
    #pragma unroll
    for (int j = 1; j < TOK; j++) m = fmaxf(m, s[j]);
    #pragma unroll
    for (int o = 16; o > 0; o >>= 1)
        m = fmaxf(m, __shfl_xor_sync(0xffffffffu, m, o));
    if (lane == 0) sred[wid] = m;
    __syncthreads();
    if (wid == 0) {
        float mm = sred[lane];   // 32 warps -> 32 lanes
        #pragma unroll
        for (int o = 16; o > 0; o >>= 1)
            mm = fmaxf(mm, __shfl_xor_sync(0xffffffffu, mm, o));
        if (lane == 0) sbc[0] = mm;
    }
    __syncthreads();
    const float gmax = sbc[0];

    // ---------- Phase B: exp + fused value accumulation ----------
    float e_[TOK];
    float csum = 0.0f;
    float cv[16];
    #pragma unroll
    for (int i = 0; i < 16; i++) cv[i] = 0.0f;

    #pragma unroll
    for (int j = 0; j < TOK; j++) {
        const int t = tid + j * NTHREADS;
        const float e = ex2f_((s[j] - gmax) * 1.4426950408889634f);
        e_[j] = e;
        csum += e;
        const float4* vp =
            reinterpret_cast<const float4*>(value + ((size_t)b * NT + t) * 16);
        const float4 v0 = vp[0], v1 = vp[1], v2 = vp[2], v3 = vp[3];
        cv[0]  = fmaf(e, v0.x, cv[0]);  cv[1]  = fmaf(e, v0.y, cv[1]);
        cv[2]  = fmaf(e, v0.z, cv[2]);  cv[3]  = fmaf(e, v0.w, cv[3]);
        cv[4]  = fmaf(e, v1.x, cv[4]);  cv[5]  = fmaf(e, v1.y, cv[5]);
        cv[6]  = fmaf(e, v1.z, cv[6]);  cv[7]  = fmaf(e, v1.w, cv[7]);
        cv[8]  = fmaf(e, v2.x, cv[8]);  cv[9]  = fmaf(e, v2.y, cv[9]);
        cv[10] = fmaf(e, v2.z, cv[10]); cv[11] = fmaf(e, v2.w, cv[11]);
        cv[12] = fmaf(e, v3.x, cv[12]); cv[13] = fmaf(e, v3.y, cv[13]);
        cv[14] = fmaf(e, v3.z, cv[14]); cv[15] = fmaf(e, v3.w, cv[15]);
    }

    // ---------- Deterministic 17-value reduction (sum + ctx[16]) ----------
    #pragma unroll
    for (int o = 16; o > 0; o >>= 1) {
        csum += __shfl_xor_sync(0xffffffffu, csum, o);
        #pragma unroll
        for (int i = 0; i < 16; i++)
            cv[i] += __shfl_xor_sync(0xffffffffu, cv[i], o);
    }
    if (lane == 0) {
        sred[wid * 17] = csum;
        #pragma unroll
        for (int i = 0; i < 16; i++) sred[wid * 17 + 1 + i] = cv[i];
    }
    __syncthreads();
    if (tid < 17) {
        float a = sred[tid];
        #pragma unroll
        for (int w = 1; w < 32; w++) a += sred[w * 17 + tid];
        sbc[1 + tid] = a;    // sbc[1]=sum, sbc[2..17]=ctx
    }
    __syncthreads();

    const float inv = rcpf_(sbc[1]);

    #pragma unroll
    for (int j = 0; j < TOK; j++)
        out_attn[(size_t)b * NT + tid + j * NTHREADS] = e_[j] * inv;

    if (tid >= 1 && tid < 17)
        out_ctx[b * 16 + (tid - 1)] = sbc[1 + tid] * inv;
}

extern "C" void kernel_launch(void* const* d_in, const int* in_sizes, int n_in,
                              void* d_out, int out_size) {
    const float* query = (const float*)d_in[0];
    const float* key   = (const float*)d_in[1];
    const float* value = (const float*)d_in[2];
    const float* W1    = (const float*)d_in[3];
    const float* W2    = (const float*)d_in[4];
    const float* bias  = (const float*)d_in[5];
    const float* v_w   = (const float*)d_in[6];
    const float* v_b   = (const float*)d_in[7];

    float* out_ctx  = (float*)d_out;            // [B,1,16] -> 2048 floats
    float* out_attn = (float*)d_out + NB * 16;  // [B,T]    -> 524288 floats

    additive_attn_fused<<<NB, NTHREADS>>>(query, key, value, W1, W2,
                                          bias, v_w, v_b, out_ctx, out_attn);
}

// round 2
// speedup vs baseline: 1.1307x; 1.1307x over previous
#include <cuda_runtime.h>

typedef unsigned long long ull;

#define NB 128
#define NT 4096
#define NTH 1024          // threads per CTA; 4 tokens/thread

__device__ __forceinline__ float ex2f_(float x) {
    float y; asm("ex2.approx.f32 %0, %1;" : "=f"(y) : "f"(x)); return y;
}
__device__ __forceinline__ float rcpf_(float x) {
    float y; asm("rcp.approx.f32 %0, %1;" : "=f"(y) : "f"(x)); return y;
}
// packed f32x2 fma: d = a*b + d  (2 FMAs per issue slot)
__device__ __forceinline__ void pfma(ull& d, ull a, ull b) {
    asm("fma.rn.f32x2 %0, %1, %2, %0;" : "+l"(d) : "l"(a), "l"(b));
}
__device__ __forceinline__ ull pack2(float a, float b) {
    ull p; asm("mov.b64 %0, {%1, %2};" : "=l"(p) : "f"(a), "f"(b)); return p;
}
__device__ __forceinline__ float2 unpack2(ull p) {
    float2 r; asm("mov.b64 {%0, %1}, %2;" : "=f"(r.x), "=f"(r.y) : "l"(p)); return r;
}

__global__ void __launch_bounds__(NTH, 1)
additive_attn_fused(const float* __restrict__ query,   // [B,1,16]
                    const float* __restrict__ key,     // [B,T,16]
                    const float* __restrict__ value,   // [B,T,16]
                    const float* __restrict__ W1,      // [32,16]
                    const float* __restrict__ W2,      // [32,16]
                    const float* __restrict__ bias,    // scalar
                    const float* __restrict__ v_w,     // [1,32]
                    const float* __restrict__ v_b,     // [1]
                    float* __restrict__ out_ctx,       // [B,16]
                    float* __restrict__ out_attn)      // [B,T]
{
    const int b    = blockIdx.x;
    const int tid  = threadIdx.x;
    const int lane = tid & 31;
    const int wid  = tid >> 5;

    // W2 rows pre-scaled by 2*log2(e), stored as packed f32x2 pairs
    __shared__ ull   sW2p[32 * 8];    // [row][pair0..7]
    __shared__ ull   sc0[32];         // (2log2e*(qproj_w + bias), 0) packed
    __shared__ float sv2[32];         // -2 * v_w[w]
    __shared__ float ssv;             // v_b + sum(v_w)
    __shared__ float sred[32 * 17];
    __shared__ float sbc[18];         // [0]=max, [1]=sum, [2..17]=ctx

    const float S = 2.885390081777927f;   // 2*log2(e)

    if (tid < 128) {
        // float4 index tid -> row tid/4, quarter tid%4 -> pairs 2*tid, 2*tid+1
        float4 wr = reinterpret_cast<const float4*>(W2)[tid];
        sW2p[tid * 2 + 0] = pack2(S * wr.x, S * wr.y);
        sW2p[tid * 2 + 1] = pack2(S * wr.z, S * wr.w);
    }
    if (tid >= 128 && tid < 160) {
        const int w = tid - 128;
        const float vw = v_w[w];
        sv2[w] = -2.0f * vw;
        float s = vw;
        #pragma unroll
        for (int o = 16; o > 0; o >>= 1)
            s += __shfl_xor_sync(0xffffffffu, s, o);
        if (w == 0) ssv = v_b[0] + s;
    }
    if (tid >= 160 && tid < 192) {
        const int w = tid - 160;
        float acc = *bias;
        #pragma unroll
        for (int d = 0; d < 16; d++)
            acc = fmaf(query[b * 16 + d], W1[w * 16 + d], acc);
        sc0[w] = pack2(S * acc, 0.0f);
    }
    __syncthreads();

    const float svsum = ssv;

    // ---------- Phase A: scores; 2 tokens share each W2-row load ----------
    float s[4];
    #pragma unroll
    for (int jp = 0; jp < 2; jp++) {
        const int t0 = tid + (2 * jp + 0) * NTH;
        const int t1 = tid + (2 * jp + 1) * NTH;
        const ulonglong2* kp0 =
            reinterpret_cast<const ulonglong2*>(key + ((size_t)b * NT + t0) * 16);
        const ulonglong2* kp1 =
            reinterpret_cast<const ulonglong2*>(key + ((size_t)b * NT + t1) * 16);
        ull ka[8], kb[8];
        #pragma unroll
        for (int i = 0; i < 4; i++) {
            ulonglong2 va = kp0[i]; ka[2*i] = va.x; ka[2*i+1] = va.y;
            ulonglong2 vb_ = kp1[i]; kb[2*i] = vb_.x; kb[2*i+1] = vb_.y;
        }

        float a0 = svsum, a1 = svsum;
        #pragma unroll 4
        for (int w = 0; w < 32; w++) {
            ull acc0 = sc0[w];
            ull acc1 = acc0;
            const ulonglong2* wr =
                reinterpret_cast<const ulonglong2*>(&sW2p[w * 8]);
            ulonglong2 wv = wr[0];
            pfma(acc0, ka[0], wv.x); pfma(acc1, kb[0], wv.x);
            pfma(acc0, ka[1], wv.y); pfma(acc1, kb[1], wv.y);
            wv = wr[1];
            pfma(acc0, ka[2], wv.x); pfma(acc1, kb[2], wv.x);
            pfma(acc0, ka[3], wv.y); pfma(acc1, kb[3], wv.y);
            wv = wr[2];
            pfma(acc0, ka[4], wv.x); pfma(acc1, kb[4], wv.x);
            pfma(acc0, ka[5], wv.y); pfma(acc1, kb[5], wv.y);
            wv = wr[3];
            pfma(acc0, ka[6], wv.x); pfma(acc1, kb[6], wv.x);
            pfma(acc0, ka[7], wv.y); pfma(acc1, kb[7], wv.y);

            const float2 h0 = unpack2(acc0);
            const float2 h1 = unpack2(acc1);
            const float A0 = h0.x + h0.y;       // = 2log2e*(kproj+qproj+bias)
            const float A1 = h1.x + h1.y;
            const float r0 = rcpf_(ex2f_(A0) + 1.0f);
            const float r1 = rcpf_(ex2f_(A1) + 1.0f);
            const float v2 = sv2[w];
            a0 = fmaf(v2, r0, a0);              // score += -2*sv*r  (tanh folded)
            a1 = fmaf(v2, r1, a1);
        }
        s[2 * jp + 0] = a0;
        s[2 * jp + 1] = a1;
    }

    // ---------- Block max (exact, deterministic) ----------
    float m = fmaxf(fmaxf(s[0], s[1]), fmaxf(s[2], s[3]));
    #pragma unroll
    for (int o = 16; o > 0; o >>= 1)
        m = fmaxf(m, __shfl_xor_sync(0xffffffffu, m, o));
    if (lane == 0) sred[wid] = m;
    __syncthreads();
    if (wid == 0) {
        float mm = sred[lane];
        #pragma unroll
        for (int o = 16; o > 0; o >>= 1)
            mm = fmaxf(mm, __shfl_xor_sync(0xffffffffu, mm, o));
        if (lane == 0) sbc[0] = mm;
    }
    __syncthreads();
    const float L = 1.4426950408889634f;
    const float negmL = -sbc[0] * L;

    // ---------- Phase B: exp + packed value accumulation ----------
    float e_[4];
    float csum = 0.0f;
    ull cv[8];
    #pragma unroll
    for (int i = 0; i < 8; i++) cv[i] = 0ull;

    #pragma unroll
    for (int j = 0; j < 4; j++) {
        const int t = tid + j * NTH;
        const float e = ex2f_(fmaf(s[j], L, negmL));
        e_[j] = e;
        csum += e;
        const ull ee = pack2(e, e);
        const ulonglong2* vp =
            reinterpret_cast<const ulonglong2*>(value + ((size_t)b * NT + t) * 16);
        #pragma unroll
        for (int i = 0; i < 4; i++) {
            ulonglong2 vv = vp[i];
            pfma(cv[2*i],   ee, vv.x);
            pfma(cv[2*i+1], ee, vv.y);
        }
    }

    // unpack ctx accumulators to 16 scalars
    float cvf[16];
    #pragma unroll
    for (int i = 0; i < 8; i++) {
        float2 u = unpack2(cv[i]);
        cvf[2*i] = u.x; cvf[2*i+1] = u.y;
    }

    // ---------- Deterministic 17-value reduction ----------
    #pragma unroll
    for (int o = 16; o > 0; o >>= 1) {
        csum += __shfl_xor_sync(0xffffffffu, csum, o);
        #pragma unroll
        for (int i = 0; i < 16; i++)
            cvf[i] += __shfl_xor_sync(0xffffffffu, cvf[i], o);
    }
    if (lane == 0) {
        sred[wid * 17] = csum;
        #pragma unroll
        for (int i = 0; i < 16; i++) sred[wid * 17 + 1 + i] = cvf[i];
    }
    __syncthreads();
    if (tid < 17) {
        float a = sred[tid];
        #pragma unroll
        for (int w = 1; w < 32; w++) a += sred[w * 17 + tid];
        sbc[1 + tid] = a;
    }
    __syncthreads();

    const float inv = rcpf_(sbc[1]);

    #pragma unroll
    for (int j = 0; j < 4; j++)
        out_attn[(size_t)b * NT + tid + j * NTH] = e_[j] * inv;

    if (tid >= 1 && tid < 17)
        out_ctx[b * 16 + (tid - 1)] = sbc[1 + tid] * inv;
}

extern "C" void kernel_launch(void* const* d_in, const int* in_sizes, int n_in,
                              void* d_out, int out_size) {
    const float* query = (const float*)d_in[0];
    const float* key   = (const float*)d_in[1];
    const float* value = (const float*)d_in[2];
    const float* W1    = (const float*)d_in[3];
    const float* W2    = (const float*)d_in[4];
    const float* bias  = (const float*)d_in[5];
    const float* v_w   = (const float*)d_in[6];
    const float* v_b   = (const float*)d_in[7];

    float* out_ctx  = (float*)d_out;            // [B,1,16]
    float* out_attn = (float*)d_out + NB * 16;  // [B,T]

    additive_attn_fused<<<NB, NTH>>>(query, key, value, W1, W2,
                                     bias, v_w, v_b, out_ctx, out_attn);
}

// round 3
// speedup vs baseline: 1.2880x; 1.1391x over previous
#include <cuda_runtime.h>

typedef unsigned long long ull;

#define NB 128
#define NT 4096
#define NTH 1024          // threads per CTA; 4 tokens/thread

__device__ __forceinline__ float ex2f_(float x) {
    float y; asm("ex2.approx.f32 %0, %1;" : "=f"(y) : "f"(x)); return y;
}
__device__ __forceinline__ float rcpf_(float x) {
    float y; asm("rcp.approx.f32 %0, %1;" : "=f"(y) : "f"(x)); return y;
}
__device__ __forceinline__ float tanhf_(float x) {
    float y; asm("tanh.approx.f32 %0, %1;" : "=f"(y) : "f"(x)); return y;
}
// packed f32x2 fma: d = a*b + d  (2 FMAs per issue slot)
__device__ __forceinline__ void pfma(ull& d, ull a, ull b) {
    asm("fma.rn.f32x2 %0, %1, %2, %0;" : "+l"(d) : "l"(a), "l"(b));
}
__device__ __forceinline__ ull pack2(float a, float b) {
    ull p; asm("mov.b64 %0, {%1, %2};" : "=l"(p) : "f"(a), "f"(b)); return p;
}
__device__ __forceinline__ float2 unpack2(ull p) {
    float2 r; asm("mov.b64 {%0, %1}, %2;" : "=f"(r.x), "=f"(r.y) : "l"(p)); return r;
}

__global__ void __launch_bounds__(NTH, 1)
additive_attn_fused(const float* __restrict__ query,   // [B,1,16]
                    const float* __restrict__ key,     // [B,T,16]
                    const float* __restrict__ value,   // [B,T,16]
                    const float* __restrict__ W1,      // [32,16]
                    const float* __restrict__ W2,      // [32,16]
                    const float* __restrict__ bias,    // scalar
                    const float* __restrict__ v_w,     // [1,32]
                    const float* __restrict__ v_b,     // [1]
                    float* __restrict__ out_ctx,       // [B,16]
                    float* __restrict__ out_attn)      // [B,T]
{
    const int b    = blockIdx.x;
    const int tid  = threadIdx.x;
    const int lane = tid & 31;
    const int wid  = tid >> 5;

    __shared__ ull        sW2p[32 * 8];   // W2 rows as packed f32x2 pairs
    __shared__ ulonglong2 scv[32];        // .x = (qproj_w + bias, 0), .y lo = v_w[w]
    __shared__ float      sred[32 * 17];
    __shared__ float      sbc[18];        // [0]=max, [1]=sum, [2..17]=ctx

    if (tid < 128) {
        // float4 index tid -> row tid/4, quarter tid%4 -> pairs 2*tid, 2*tid+1
        float4 wr = reinterpret_cast<const float4*>(W2)[tid];
        sW2p[tid * 2 + 0] = pack2(wr.x, wr.y);
        sW2p[tid * 2 + 1] = pack2(wr.z, wr.w);
    }
    if (tid >= 160 && tid < 192) {
        const int w = tid - 160;
        float acc = *bias;
        #pragma unroll
        for (int d = 0; d < 16; d++)
            acc = fmaf(query[b * 16 + d], W1[w * 16 + d], acc);
        scv[w].x = pack2(acc, 0.0f);
        scv[w].y = pack2(v_w[w], 0.0f);
    }
    __syncthreads();

    const float vb = *v_b;

    // ---------- Phase A: scores; 2 tokens share each W2-row load ----------
    float s[4];
    #pragma unroll
    for (int jp = 0; jp < 2; jp++) {
        const int t0 = tid + (2 * jp + 0) * NTH;
        const int t1 = tid + (2 * jp + 1) * NTH;
        const ulonglong2* kp0 =
            reinterpret_cast<const ulonglong2*>(key + ((size_t)b * NT + t0) * 16);
        const ulonglong2* kp1 =
            reinterpret_cast<const ulonglong2*>(key + ((size_t)b * NT + t1) * 16);
        ull ka[8], kb[8];
        #pragma unroll
        for (int i = 0; i < 4; i++) {
            ulonglong2 va = kp0[i]; ka[2*i] = va.x; ka[2*i+1] = va.y;
            ulonglong2 vb_ = kp1[i]; kb[2*i] = vb_.x; kb[2*i+1] = vb_.y;
        }

        float a0 = vb, a1 = vb;
        #pragma unroll 4
        for (int w = 0; w < 32; w++) {
            const ulonglong2 cc = scv[w];           // one LDS.128: qproj pair + v_w
            ull acc0 = cc.x;
            ull acc1 = cc.x;
            const float vw = unpack2(cc.y).x;
            const ulonglong2* wr =
                reinterpret_cast<const ulonglong2*>(&sW2p[w * 8]);
            ulonglong2 wv = wr[0];
            pfma(acc0, ka[0], wv.x); pfma(acc1, kb[0], wv.x);
            pfma(acc0, ka[1], wv.y); pfma(acc1, kb[1], wv.y);
            wv = wr[1];
            pfma(acc0, ka[2], wv.x); pfma(acc1, kb[2], wv.x);
            pfma(acc0, ka[3], wv.y); pfma(acc1, kb[3], wv.y);
            wv = wr[2];
            pfma(acc0, ka[4], wv.x); pfma(acc1, kb[4], wv.x);
            pfma(acc0, ka[5], wv.y); pfma(acc1, kb[5], wv.y);
            wv = wr[3];
            pfma(acc0, ka[6], wv.x); pfma(acc1, kb[6], wv.x);
            pfma(acc0, ka[7], wv.y); pfma(acc1, kb[7], wv.y);

            const float2 h0 = unpack2(acc0);
            const float2 h1 = unpack2(acc1);
            const float t0h = tanhf_(h0.x + h0.y);  // tanh(kproj + qproj + bias)
            const float t1h = tanhf_(h1.x + h1.y);
            a0 = fmaf(vw, t0h, a0);
            a1 = fmaf(vw, t1h, a1);
        }
        s[2 * jp + 0] = a0;
        s[2 * jp + 1] = a1;
    }

    // ---------- Block max (exact, deterministic) ----------
    float m = fmaxf(fmaxf(s[0], s[1]), fmaxf(s[2], s[3]));
    #pragma unroll
    for (int o = 16; o > 0; o >>= 1)
        m = fmaxf(m, __shfl_xor_sync(0xffffffffu, m, o));
    if (lane == 0) sred[wid] = m;
    __syncthreads();
    if (wid == 0) {
        float mm = sred[lane];
        #pragma unroll
        for (int o = 16; o > 0; o >>= 1)
            mm = fmaxf(mm, __shfl_xor_sync(0xffffffffu, mm, o));
        if (lane == 0) sbc[0] = mm;
    }
    __syncthreads();
    const float L = 1.4426950408889634f;
    const float negmL = -sbc[0] * L;

    // ---------- Phase B: exp + packed value accumulation ----------
    float e_[4];
    float csum = 0.0f;
    ull cv[8];
    #pragma unroll
    for (int i = 0; i < 8; i++) cv[i] = 0ull;

    #pragma unroll
    for (int j = 0; j < 4; j++) {
        const int t = tid + j * NTH;
        const float e = ex2f_(fmaf(s[j], L, negmL));
        e_[j] = e;
        csum += e;
        const ull ee = pack2(e, e);
        const ulonglong2* vp =
            reinterpret_cast<const ulonglong2*>(value + ((size_t)b * NT + t) * 16);
        #pragma unroll
        for (int i = 0; i < 4; i++) {
            ulonglong2 vv = vp[i];
            pfma(cv[2*i],   ee, vv.x);
            pfma(cv[2*i+1], ee, vv.y);
        }
    }

    // unpack ctx accumulators to 16 scalars
    float cvf[16];
    #pragma unroll
    for (int i = 0; i < 8; i++) {
        float2 u = unpack2(cv[i]);
        cvf[2*i] = u.x; cvf[2*i+1] = u.y;
    }

    // ---------- Deterministic 17-value reduction ----------
    #pragma unroll
    for (int o = 16; o > 0; o >>= 1) {
        csum += __shfl_xor_sync(0xffffffffu, csum, o);
        #pragma unroll
        for (int i = 0; i < 16; i++)
            cvf[i] += __shfl_xor_sync(0xffffffffu, cvf[i], o);
    }
    if (lane == 0) {
        sred[wid * 17] = csum;
        #pragma unroll
        for (int i = 0; i < 16; i++) sred[wid * 17 + 1 + i] = cvf[i];
    }
    __syncthreads();
    if (tid < 17) {
        float a = sred[tid];
        #pragma unroll
        for (int w = 1; w < 32; w++) a += sred[w * 17 + tid];
        sbc[1 + tid] = a;
    }
    __syncthreads();

    const float inv = rcpf_(sbc[1]);

    #pragma unroll
    for (int j = 0; j < 4; j++)
        out_attn[(size_t)b * NT + tid + j * NTH] = e_[j] * inv;

    if (tid >= 1 && tid < 17)
        out_ctx[b * 16 + (tid - 1)] = sbc[1 + tid] * inv;
}

extern "C" void kernel_launch(void* const* d_in, const int* in_sizes, int n_in,
                              void* d_out, int out_size) {
    const float* query = (const float*)d_in[0];
    const float* key   = (const float*)d_in[1];
    const float* value = (const float*)d_in[2];
    const float* W1    = (const float*)d_in[3];
    const float* W2    = (const float*)d_in[4];
    const float* bias  = (const float*)d_in[5];
    const float* v_w   = (const float*)d_in[6];
    const float* v_b   = (const float*)d_in[7];

    float* out_ctx  = (float*)d_out;            // [B,1,16]
    float* out_attn = (float*)d_out + NB * 16;  // [B,T]

    additive_attn_fused<<<NB, NTH>>>(query, key, value, W1, W2,
                                     bias, v_w, v_b, out_ctx, out_attn);
}